// round 16
// baseline (speedup 1.0000x reference)
#include <cuda_runtime.h>
#include <cstdint>

// spspmm: coarse target-bucketing (8 buckets, 32MB L2-resident output slices),
// uint64-packed (a,c,d), 2 pairs per 8-thread group via one 16B load, __ldcs
// streaming gathers, guarded red.global.add.v4.f32, inline overlapped
// next-slice zeroing. 128-thread pairs blocks for fine retire granularity;
// vectorized (2 pairs/thread) scatter.

#define NB      8
#define CAP     560000          // per-bucket capacity (expected max ~524K+36K)

__device__ int  g_bcursor[NB];
__device__ __align__(16) unsigned long long g_pk[NB * CAP];   // packed (a,c,d)

__global__ void init_kernel() {
    if (threadIdx.x < NB) g_bcursor[threadIdx.x] = 0;
}

// Block-aggregated bucket scatter (2 pairs per thread) + zero output slice 0.
__global__ void __launch_bounds__(256) scatter_kernel(
    const int* __restrict__ acd, int M, int bshift,
    int sh_c, int sh_d,
    float4* __restrict__ out4, long long z0_end)
{
    __shared__ int s_cnt[NB];
    __shared__ int s_base[NB];
    int t = blockIdx.x * blockDim.x + threadIdx.x;
    int i0 = t * 2;

    if (threadIdx.x < NB) s_cnt[threadIdx.x] = 0;
    __syncthreads();

    int n = 0;                       // pairs handled by this thread (0..2)
    int a0 = 0, a1 = 0, b0 = 0, b1 = 0, p0 = 0, p1 = 0;
    unsigned long long pk0 = 0, pk1 = 0;
    if (i0 + 1 < M) {
        int2 av = *(const int2*)&acd[i0];
        int2 cv = *(const int2*)&acd[M + i0];
        int2 dv = *(const int2*)&acd[2 * M + i0];
        a0 = av.x; a1 = av.y;
        pk0 = (unsigned long long)(unsigned)av.x
            | ((unsigned long long)(unsigned)cv.x << sh_c)
            | ((unsigned long long)(unsigned)dv.x << sh_d);
        pk1 = (unsigned long long)(unsigned)av.y
            | ((unsigned long long)(unsigned)cv.y << sh_c)
            | ((unsigned long long)(unsigned)dv.y << sh_d);
        n = 2;
    } else if (i0 < M) {
        a0 = acd[i0];
        pk0 = (unsigned long long)(unsigned)a0
            | ((unsigned long long)(unsigned)acd[M + i0] << sh_c)
            | ((unsigned long long)(unsigned)acd[2 * M + i0] << sh_d);
        n = 1;
    }
    if (n >= 1) { b0 = a0 >> bshift; p0 = atomicAdd(&s_cnt[b0], 1); }
    if (n == 2) { b1 = a1 >> bshift; p1 = atomicAdd(&s_cnt[b1], 1); }
    __syncthreads();
    if (threadIdx.x < NB && s_cnt[threadIdx.x] > 0)
        s_base[threadIdx.x] = atomicAdd(&g_bcursor[threadIdx.x], s_cnt[threadIdx.x]);
    __syncthreads();
    if (n >= 1) g_pk[b0 * CAP + s_base[b0] + p0] = pk0;
    if (n == 2) g_pk[b1 * CAP + s_base[b1] + p1] = pk1;

    // Zero slice 0 (grid-stride, default policy -> stays L2-resident).
    float4 z = make_float4(0.f, 0.f, 0.f, 0.f);
    long long stride = (long long)gridDim.x * blockDim.x;
    for (long long j = t; j < z0_end; j += stride) out4[j] = z;
}

// Pairs for bucket b: inline zero of slice b+1, then 2 pairs per 8-thr group
// fetched with a single 16B packed-index load. 128-thread blocks.
__global__ void __launch_bounds__(128) pairs_kernel(
    const float4* __restrict__ A,
    const float4* __restrict__ B,
    float* __restrict__ out,
    int b, int sh_c, int sh_d, unsigned mask,
    long long znext0, long long znext1)
{
    long long gid = (long long)blockIdx.x * blockDim.x + threadIdx.x;
    long long stride = (long long)gridDim.x * blockDim.x;

    // Zero the NEXT bucket's output slice (grid-stride: ~1 float4 per thread,
    // naturally overlapped with the gathers; disjoint from this bucket's REDs).
    {
        float4 z = make_float4(0.f, 0.f, 0.f, 0.f);
        float4* out4 = (float4*)out;
        for (long long j = znext0 + gid; j < znext1; j += stride) out4[j] = z;
    }

    int cnt = g_bcursor[b];          // broadcast load
    int grp = (int)(gid >> 3);
    int f = (int)(gid & 7);
    int p0 = grp * 2;
    if (p0 >= cnt) return;

    int e = cnt - 1 - p0;            // >= 0; second pair valid iff e >= 1

    // ONE 16B broadcast load covering both pairs (p0 even -> aligned).
    ulonglong2 k = __ldg((const ulonglong2*)&g_pk[b * CAP + p0]);

    int a0 = (int)((unsigned)k.x & mask);
    int c0 = (int)((unsigned)(k.x >> sh_c) & mask);
    int d0 = (int)((unsigned)(k.x >> sh_d) & mask);
    int a1 = (int)((unsigned)k.y & mask);
    int c1 = (int)((unsigned)(k.y >> sh_c) & mask);
    int d1 = (int)((unsigned)(k.y >> sh_d) & mask);
    if (e < 1) { c1 = c0; d1 = d0; }   // keep addresses safe for the prefetch

    // 4 independent streaming gathers in flight.
    float4 av0 = __ldcs(&A[(long long)c0 * 8 + f]);
    float4 bv0 = __ldcs(&B[(long long)d0 * 8 + f]);
    float4 av1 = __ldcs(&A[(long long)c1 * 8 + f]);
    float4 bv1 = __ldcs(&B[(long long)d1 * 8 + f]);

    float4 m;
    m.x = av0.x * bv0.x; m.y = av0.y * bv0.y;
    m.z = av0.z * bv0.z; m.w = av0.w * bv0.w;
    {
        float* dst = out + (long long)a0 * 32 + f * 4;
        asm volatile("red.global.add.v4.f32 [%0], {%1, %2, %3, %4};"
                     :: "l"(dst), "f"(m.x), "f"(m.y), "f"(m.z), "f"(m.w) : "memory");
    }
    if (e >= 1) {
        m.x = av1.x * bv1.x; m.y = av1.y * bv1.y;
        m.z = av1.z * bv1.z; m.w = av1.w * bv1.w;
        float* dst = out + (long long)a1 * 32 + f * 4;
        asm volatile("red.global.add.v4.f32 [%0], {%1, %2, %3, %4};"
                     :: "l"(dst), "f"(m.x), "f"(m.y), "f"(m.z), "f"(m.w) : "memory");
    }
}

static inline int ceil_log2(long long v) {
    int b = 0;
    while ((1LL << b) < v) b++;
    return b;
}

extern "C" void kernel_launch(void* const* d_in, const int* in_sizes, int n_in,
                              void* d_out, int out_size) {
    const float4* A = (const float4*)d_in[0];
    const float4* B = (const float4*)d_in[1];
    const int* acd = (const int*)d_in[2];
    float* out = (float*)d_out;

    int M = in_sizes[2] / 3;
    int tar = out_size / 32;
    long long nnzA = (long long)in_sizes[0] / 32;
    long long nnzB = (long long)in_sizes[1] / 32;

    // Packing layout: a | c<<w | d<<2w (uniform field width).
    int ba = ceil_log2(tar);
    int bc = ceil_log2(nnzA);
    int bd = ceil_log2(nnzB);
    int w = ba > bc ? ba : bc;
    if (bd > w) w = bd;
    if (3 * w > 64 || w > 31) return;     // never hit for this problem
    int sh_c = w, sh_d = 2 * w;
    unsigned mask = (w == 32) ? 0xFFFFFFFFu : ((1u << w) - 1u);

    // Bucket size = pow2 >= ceil(tar/NB); bucket id = a >> bshift.
    int bsize_min = (tar + NB - 1) / NB;
    int bshift = 0;
    while ((1 << bshift) < bsize_min) bshift++;
    int bsize = 1 << bshift;
    int nb = (tar + bsize - 1) >> bshift;   // <= NB

    init_kernel<<<1, 32>>>();

    long long z0_end = (long long)((bsize < tar) ? bsize : tar) * 8;
    int sthreads = (M + 1) / 2;
    scatter_kernel<<<(sthreads + 255) / 256, 256>>>(acd, M, bshift, sh_c, sh_d,
                                                    (float4*)d_out, z0_end);

    // 2 pairs per 8-thread group; 128-thread blocks.
    int pair_blocks = ((CAP + 1) / 2 * 8 + 127) / 128;
    for (int b = 0; b < nb; b++) {
        long long s = (long long)(b + 1) << bshift;
        long long e = (long long)(b + 2) << bshift;
        if (s > tar) s = tar;
        if (e > tar) e = tar;
        long long zn0 = s * 8, zn1 = e * 8;   // empty when b+1 >= nb
        pairs_kernel<<<pair_blocks, 128>>>(A, B, out, b, sh_c, sh_d, mask,
                                           zn0, zn1);
    }
}

// round 17
// speedup vs baseline: 1.2366x; 1.2366x over previous
#include <cuda_runtime.h>
#include <cstdint>

// spspmm: coarse target-bucketing (8 buckets, 32MB L2-resident output slices),
// uint64-packed (a,c,d) indices, 2 pairs per 8-thread group via one 16B load,
// __ldcs streaming gathers, guarded red.global.add.v4.f32, inline overlapped
// next-slice zeroing. 256-thread pairs blocks (R13 optimum); vectorized
// (2 pairs/thread) scatter.

#define NB      8
#define CAP     560000          // per-bucket capacity (expected max ~524K+36K)

__device__ int  g_bcursor[NB];
__device__ __align__(16) unsigned long long g_pk[NB * CAP];   // packed (a,c,d)

__global__ void init_kernel() {
    if (threadIdx.x < NB) g_bcursor[threadIdx.x] = 0;
}

// Block-aggregated bucket scatter (2 pairs per thread) + zero output slice 0.
__global__ void __launch_bounds__(256) scatter_kernel(
    const int* __restrict__ acd, int M, int bshift,
    int sh_c, int sh_d,
    float4* __restrict__ out4, long long z0_end)
{
    __shared__ int s_cnt[NB];
    __shared__ int s_base[NB];
    int t = blockIdx.x * blockDim.x + threadIdx.x;
    int i0 = t * 2;

    if (threadIdx.x < NB) s_cnt[threadIdx.x] = 0;
    __syncthreads();

    int n = 0;                       // pairs handled by this thread (0..2)
    int a0 = 0, a1 = 0, b0 = 0, b1 = 0, p0 = 0, p1 = 0;
    unsigned long long pk0 = 0, pk1 = 0;
    if (i0 + 1 < M) {
        int2 av = *(const int2*)&acd[i0];
        int2 cv = *(const int2*)&acd[M + i0];
        int2 dv = *(const int2*)&acd[2 * M + i0];
        a0 = av.x; a1 = av.y;
        pk0 = (unsigned long long)(unsigned)av.x
            | ((unsigned long long)(unsigned)cv.x << sh_c)
            | ((unsigned long long)(unsigned)dv.x << sh_d);
        pk1 = (unsigned long long)(unsigned)av.y
            | ((unsigned long long)(unsigned)cv.y << sh_c)
            | ((unsigned long long)(unsigned)dv.y << sh_d);
        n = 2;
    } else if (i0 < M) {
        a0 = acd[i0];
        pk0 = (unsigned long long)(unsigned)a0
            | ((unsigned long long)(unsigned)acd[M + i0] << sh_c)
            | ((unsigned long long)(unsigned)acd[2 * M + i0] << sh_d);
        n = 1;
    }
    if (n >= 1) { b0 = a0 >> bshift; p0 = atomicAdd(&s_cnt[b0], 1); }
    if (n == 2) { b1 = a1 >> bshift; p1 = atomicAdd(&s_cnt[b1], 1); }
    __syncthreads();
    if (threadIdx.x < NB && s_cnt[threadIdx.x] > 0)
        s_base[threadIdx.x] = atomicAdd(&g_bcursor[threadIdx.x], s_cnt[threadIdx.x]);
    __syncthreads();
    if (n >= 1) __stcs(&g_pk[b0 * CAP + s_base[b0] + p0], pk0);
    if (n == 2) __stcs(&g_pk[b1 * CAP + s_base[b1] + p1], pk1);

    // Zero slice 0 (grid-stride, default policy -> stays L2-resident).
    float4 z = make_float4(0.f, 0.f, 0.f, 0.f);
    long long stride = (long long)gridDim.x * blockDim.x;
    for (long long j = t; j < z0_end; j += stride) out4[j] = z;
}

// Pairs for bucket b: inline zero of slice b+1, then 2 pairs per 8-thr group
// fetched with a single 16B packed-index load. 256-thread blocks (optimum).
__global__ void __launch_bounds__(256) pairs_kernel(
    const float4* __restrict__ A,
    const float4* __restrict__ B,
    float* __restrict__ out,
    int b, int sh_c, int sh_d, unsigned mask,
    long long znext0, long long znext1)
{
    long long gid = (long long)blockIdx.x * blockDim.x + threadIdx.x;
    long long stride = (long long)gridDim.x * blockDim.x;

    // Zero the NEXT bucket's output slice (grid-stride: ~1 float4 per thread,
    // naturally overlapped with the gathers; disjoint from this bucket's REDs).
    {
        float4 z = make_float4(0.f, 0.f, 0.f, 0.f);
        float4* out4 = (float4*)out;
        for (long long j = znext0 + gid; j < znext1; j += stride) out4[j] = z;
    }

    int cnt = g_bcursor[b];          // broadcast load
    int grp = (int)(gid >> 3);
    int f = (int)(gid & 7);
    int p0 = grp * 2;
    if (p0 >= cnt) return;

    int e = cnt - 1 - p0;            // >= 0; second pair valid iff e >= 1

    // ONE 16B broadcast load covering both pairs (p0 even -> aligned).
    ulonglong2 k = __ldg((const ulonglong2*)&g_pk[b * CAP + p0]);

    int a0 = (int)((unsigned)k.x & mask);
    int c0 = (int)((unsigned)(k.x >> sh_c) & mask);
    int d0 = (int)((unsigned)(k.x >> sh_d) & mask);
    int a1 = (int)((unsigned)k.y & mask);
    int c1 = (int)((unsigned)(k.y >> sh_c) & mask);
    int d1 = (int)((unsigned)(k.y >> sh_d) & mask);
    if (e < 1) { c1 = c0; d1 = d0; }   // keep addresses safe for the prefetch

    // 4 independent streaming gathers in flight.
    float4 av0 = __ldcs(&A[(long long)c0 * 8 + f]);
    float4 bv0 = __ldcs(&B[(long long)d0 * 8 + f]);
    float4 av1 = __ldcs(&A[(long long)c1 * 8 + f]);
    float4 bv1 = __ldcs(&B[(long long)d1 * 8 + f]);

    float4 m;
    m.x = av0.x * bv0.x; m.y = av0.y * bv0.y;
    m.z = av0.z * bv0.z; m.w = av0.w * bv0.w;
    {
        float* dst = out + (long long)a0 * 32 + f * 4;
        asm volatile("red.global.add.v4.f32 [%0], {%1, %2, %3, %4};"
                     :: "l"(dst), "f"(m.x), "f"(m.y), "f"(m.z), "f"(m.w) : "memory");
    }
    if (e >= 1) {
        m.x = av1.x * bv1.x; m.y = av1.y * bv1.y;
        m.z = av1.z * bv1.z; m.w = av1.w * bv1.w;
        float* dst = out + (long long)a1 * 32 + f * 4;
        asm volatile("red.global.add.v4.f32 [%0], {%1, %2, %3, %4};"
                     :: "l"(dst), "f"(m.x), "f"(m.y), "f"(m.z), "f"(m.w) : "memory");
    }
}

static inline int ceil_log2(long long v) {
    int b = 0;
    while ((1LL << b) < v) b++;
    return b;
}

extern "C" void kernel_launch(void* const* d_in, const int* in_sizes, int n_in,
                              void* d_out, int out_size) {
    const float4* A = (const float4*)d_in[0];
    const float4* B = (const float4*)d_in[1];
    const int* acd = (const int*)d_in[2];
    float* out = (float*)d_out;

    int M = in_sizes[2] / 3;
    int tar = out_size / 32;
    long long nnzA = (long long)in_sizes[0] / 32;
    long long nnzB = (long long)in_sizes[1] / 32;

    // Packing layout: a | c<<w | d<<2w (uniform field width).
    int ba = ceil_log2(tar);
    int bc = ceil_log2(nnzA);
    int bd = ceil_log2(nnzB);
    int w = ba > bc ? ba : bc;
    if (bd > w) w = bd;
    if (3 * w > 64 || w > 31) return;     // never hit for this problem
    int sh_c = w, sh_d = 2 * w;
    unsigned mask = (w == 32) ? 0xFFFFFFFFu : ((1u << w) - 1u);

    // Bucket size = pow2 >= ceil(tar/NB); bucket id = a >> bshift.
    int bsize_min = (tar + NB - 1) / NB;
    int bshift = 0;
    while ((1 << bshift) < bsize_min) bshift++;
    int bsize = 1 << bshift;
    int nb = (tar + bsize - 1) >> bshift;   // <= NB

    init_kernel<<<1, 32>>>();

    long long z0_end = (long long)((bsize < tar) ? bsize : tar) * 8;
    int sthreads = (M + 1) / 2;
    scatter_kernel<<<(sthreads + 255) / 256, 256>>>(acd, M, bshift, sh_c, sh_d,
                                                    (float4*)d_out, z0_end);

    // 2 pairs per 8-thread group; 256-thread blocks.
    int pair_blocks = ((CAP + 1) / 2 * 8 + 255) / 256;
    for (int b = 0; b < nb; b++) {
        long long s = (long long)(b + 1) << bshift;
        long long e = (long long)(b + 2) << bshift;
        if (s > tar) s = tar;
        if (e > tar) e = tar;
        long long zn0 = s * 8, zn1 = e * 8;   // empty when b+1 >= nb
        pairs_kernel<<<pair_blocks, 256>>>(A, B, out, b, sh_c, sh_d, mask,
                                           zn0, zn1);
    }
}